// round 5
// baseline (speedup 1.0000x reference)
#include <cuda_runtime.h>

#define NNODES 507904
#define NEDGES 4063232
#define HID 64
#define NGRAPHS 8192
#define NPG 62
#define BN_EPS 1e-5f
#define FN ((float)NNODES)
#define APAD 68

// -------- device scratch (no allocations allowed) --------
__device__ float g_h[(size_t)NNODES * HID];     // pre-BN post-relu activations r (gather source)
__device__ float g_agg[(size_t)NNODES * HID];   // r_i + sum_{j->i} r_j  (next-layer input, pre-fold)
__device__ float g_agg1[(size_t)NNODES * 4];    // layer-1: x_i + sum x_j
__device__ float g_stat[6 * HID];               // [sum0,sq0, sum1,sq1, sum2,sq2]
__device__ int   g_deg[NNODES];

__device__ __forceinline__ void red4(float* p, float4 v) {
    asm volatile("red.global.add.v4.f32 [%0], {%1,%2,%3,%4};"
                 :: "l"(p), "f"(v.x), "f"(v.y), "f"(v.z), "f"(v.w)
                 : "memory");
}

// -------- setup kernels --------
__global__ void k_zero() {
    int i = blockIdx.x * blockDim.x + threadIdx.x;
    if (i < NNODES) g_deg[i] = 0;
    if (i < 6 * HID) g_stat[i] = 0.f;
}

__global__ void k_deg(const int* __restrict__ dst) {
    int e = blockIdx.x * blockDim.x + threadIdx.x;
    if (e < NEDGES) atomicAdd(&g_deg[dst[e]], 1);
}

__global__ void k_initagg1(const float* __restrict__ x) {
    int i = blockIdx.x * blockDim.x + threadIdx.x;
    if (i < NNODES) ((float4*)g_agg1)[i] = ((const float4*)x)[i];
}

// -------- edge scatter kernels --------
__global__ void k_edge1(const float* __restrict__ x,
                        const int* __restrict__ src, const int* __restrict__ dst) {
    int e = blockIdx.x * blockDim.x + threadIdx.x;
    if (e < NEDGES) {
        int s = src[e], d = dst[e];
        float4 v = ((const float4*)x)[s];
        red4(&g_agg1[(size_t)d * 4], v);
    }
}

// one thread per (edge, float4-chunk): 16 chunks per edge (64 ch)
__global__ void k_edge64(const int* __restrict__ src, const int* __restrict__ dst) {
    int gid = blockIdx.x * blockDim.x + threadIdx.x;
    int e = gid >> 4;
    int q = gid & 15;
    if (e < NEDGES) {
        int s = src[e], d = dst[e];
        float4 v = ((const float4*)(g_h + (size_t)s * HID))[q];
        red4(g_agg + (size_t)d * HID + (size_t)q * 4, v);
    }
}

// -------- fused GIN MLP: input-fold(BN) -> GEMM1 -> relu -> GEMM2 -> relu -> stats --------
// Block: 256 threads, 64 nodes. Thread tile: 4 nodes x 4 channels.
template<int KIN, bool BNFOLD, bool WRITE_AGG>
__global__ __launch_bounds__(256) void k_mlp(
    const float* __restrict__ Wa, const float* __restrict__ ba,
    const float* __restrict__ Wb, const float* __restrict__ bb,
    const float* __restrict__ gamma, const float* __restrict__ beta,
    int stat_in_off, int stat_out_off)
{
    __shared__ float sA[64 * APAD];
    __shared__ float sW[64 * 64];
    __shared__ float sBias[64];
    __shared__ float sS[64], sT[64], sFd[64];
    __shared__ float sStat[128];

    const int tid = threadIdx.x;
    const int nb = blockIdx.x * 64;

    if (tid < 128) sStat[tid] = 0.f;
    if (BNFOLD) {
        if (tid < 64) {
            float sum = g_stat[stat_in_off + tid];
            float sq  = g_stat[stat_in_off + 64 + tid];
            float mean = sum / FN;
            float var  = sq / FN - mean * mean;
            float inv  = rsqrtf(var + BN_EPS);
            float s    = gamma[tid] * inv;
            sS[tid] = s;
            sT[tid] = beta[tid] - mean * s;
            sFd[tid] = 1.f + (float)g_deg[nb + tid];
        }
    }
    if (tid < 64) sBias[tid] = ba[tid];
    for (int i = tid; i < KIN * 64; i += 256) sW[i] = Wa[i];
    __syncthreads();

    // load input tile (with BN fold)
    if (KIN == 4) {
        int m = tid >> 2, k = tid & 3;
        sA[m * APAD + k] = g_agg1[(size_t)(nb + m) * 4 + k];
    } else {
        for (int i = tid; i < 64 * 64; i += 256) {
            int m = i >> 6, k = i & 63;
            float v = g_agg[(size_t)(nb + m) * 64 + k];
            sA[m * APAD + k] = BNFOLD ? (sS[k] * v + sFd[m] * sT[k]) : v;
        }
    }
    __syncthreads();

    const int mt = tid >> 4;   // 0..15
    const int nt = tid & 15;   // 0..15

    float acc[4][4];
    #pragma unroll
    for (int i = 0; i < 4; i++)
        #pragma unroll
        for (int j = 0; j < 4; j++) acc[i][j] = 0.f;

    // GEMM1: [64 x KIN] @ [KIN x 64]
    #pragma unroll 4
    for (int k = 0; k < KIN; k++) {
        float a0 = sA[(mt * 4 + 0) * APAD + k];
        float a1 = sA[(mt * 4 + 1) * APAD + k];
        float a2 = sA[(mt * 4 + 2) * APAD + k];
        float a3 = sA[(mt * 4 + 3) * APAD + k];
        float4 b = *(const float4*)&sW[k * 64 + nt * 4];
        acc[0][0] += a0 * b.x; acc[0][1] += a0 * b.y; acc[0][2] += a0 * b.z; acc[0][3] += a0 * b.w;
        acc[1][0] += a1 * b.x; acc[1][1] += a1 * b.y; acc[1][2] += a1 * b.z; acc[1][3] += a1 * b.w;
        acc[2][0] += a2 * b.x; acc[2][1] += a2 * b.y; acc[2][2] += a2 * b.z; acc[2][3] += a2 * b.w;
        acc[3][0] += a3 * b.x; acc[3][1] += a3 * b.y; acc[3][2] += a3 * b.z; acc[3][3] += a3 * b.w;
    }

    // bias into regs before anyone overwrites sBias
    float bj0 = sBias[nt * 4 + 0];
    float bj1 = sBias[nt * 4 + 1];
    float bj2 = sBias[nt * 4 + 2];
    float bj3 = sBias[nt * 4 + 3];
    __syncthreads();   // done reading sA / sBias

    // mid = relu(acc + b1) -> back into sA; reload W2/b2
    #pragma unroll
    for (int i = 0; i < 4; i++) {
        float4 v;
        v.x = fmaxf(acc[i][0] + bj0, 0.f);
        v.y = fmaxf(acc[i][1] + bj1, 0.f);
        v.z = fmaxf(acc[i][2] + bj2, 0.f);
        v.w = fmaxf(acc[i][3] + bj3, 0.f);
        *(float4*)&sA[(mt * 4 + i) * APAD + nt * 4] = v;
    }
    for (int i = tid; i < 64 * 64; i += 256) sW[i] = Wb[i];
    if (tid < 64) sBias[tid] = bb[tid];
    __syncthreads();

    #pragma unroll
    for (int i = 0; i < 4; i++)
        #pragma unroll
        for (int j = 0; j < 4; j++) acc[i][j] = 0.f;

    // GEMM2: [64 x 64] @ [64 x 64]
    #pragma unroll 4
    for (int k = 0; k < 64; k++) {
        float a0 = sA[(mt * 4 + 0) * APAD + k];
        float a1 = sA[(mt * 4 + 1) * APAD + k];
        float a2 = sA[(mt * 4 + 2) * APAD + k];
        float a3 = sA[(mt * 4 + 3) * APAD + k];
        float4 b = *(const float4*)&sW[k * 64 + nt * 4];
        acc[0][0] += a0 * b.x; acc[0][1] += a0 * b.y; acc[0][2] += a0 * b.z; acc[0][3] += a0 * b.w;
        acc[1][0] += a1 * b.x; acc[1][1] += a1 * b.y; acc[1][2] += a1 * b.z; acc[1][3] += a1 * b.w;
        acc[2][0] += a2 * b.x; acc[2][1] += a2 * b.y; acc[2][2] += a2 * b.z; acc[2][3] += a2 * b.w;
        acc[3][0] += a3 * b.x; acc[3][1] += a3 * b.y; acc[3][2] += a3 * b.z; acc[3][3] += a3 * b.w;
    }

    float cj0 = sBias[nt * 4 + 0];
    float cj1 = sBias[nt * 4 + 1];
    float cj2 = sBias[nt * 4 + 2];
    float cj3 = sBias[nt * 4 + 3];

    float psum[4] = {0.f, 0.f, 0.f, 0.f};
    float psq[4]  = {0.f, 0.f, 0.f, 0.f};

    #pragma unroll
    for (int i = 0; i < 4; i++) {
        float4 v;
        v.x = fmaxf(acc[i][0] + cj0, 0.f);
        v.y = fmaxf(acc[i][1] + cj1, 0.f);
        v.z = fmaxf(acc[i][2] + cj2, 0.f);
        v.w = fmaxf(acc[i][3] + cj3, 0.f);
        size_t row = (size_t)(nb + mt * 4 + i) * 64 + (size_t)nt * 4;
        *(float4*)&g_h[row] = v;
        if (WRITE_AGG) *(float4*)&g_agg[row] = v;
        psum[0] += v.x; psq[0] += v.x * v.x;
        psum[1] += v.y; psq[1] += v.y * v.y;
        psum[2] += v.z; psq[2] += v.z * v.z;
        psum[3] += v.w; psq[3] += v.w * v.w;
    }

    // reduce lane l <-> l^16 (same nt, adjacent mt), then shared atomics
    #pragma unroll
    for (int j = 0; j < 4; j++) {
        psum[j] += __shfl_xor_sync(0xffffffffu, psum[j], 16);
        psq[j]  += __shfl_xor_sync(0xffffffffu, psq[j], 16);
    }
    if ((tid & 16) == 0) {
        #pragma unroll
        for (int j = 0; j < 4; j++) {
            atomicAdd(&sStat[nt * 4 + j], psum[j]);
            atomicAdd(&sStat[64 + nt * 4 + j], psq[j]);
        }
    }
    __syncthreads();
    if (tid < 128) atomicAdd(&g_stat[stat_out_off + tid], sStat[tid]);
}

// -------- final: BN3 + per-graph sum-pool + fc --------
__global__ __launch_bounds__(64) void k_final(
    const float* __restrict__ g3, const float* __restrict__ be3,
    const float* __restrict__ Wfc, const float* __restrict__ bfc,
    float* __restrict__ out)
{
    int g = blockIdx.x;
    int c = threadIdx.x;  // 0..63

    float sum = g_stat[4 * 64 + c];
    float sq  = g_stat[5 * 64 + c];
    float mean = sum / FN;
    float var  = sq / FN - mean * mean;
    float inv  = rsqrtf(var + BN_EPS);
    float s    = g3[c] * inv;
    float t    = be3[c] - mean * s;

    const float* base = g_h + (size_t)g * NPG * 64;
    float acc = 0.f;
    #pragma unroll 2
    for (int i = 0; i < NPG; i++) acc += base[(size_t)i * 64 + c];
    float pool = s * acc + (float)NPG * t;

    __shared__ float red[3][64];
    red[0][c] = pool * Wfc[c * 3 + 0];
    red[1][c] = pool * Wfc[c * 3 + 1];
    red[2][c] = pool * Wfc[c * 3 + 2];
    __syncthreads();
    if (c < 3) {
        float a = 0.f;
        #pragma unroll
        for (int i = 0; i < 64; i++) a += red[c][i];
        out[(size_t)g * 3 + c] = a + bfc[c];
    }
}

// -------- launch --------
extern "C" void kernel_launch(void* const* d_in, const int* in_sizes, int n_in,
                              void* d_out, int out_size) {
    (void)in_sizes; (void)n_in; (void)out_size;
    const float* x   = (const float*)d_in[0];
    const int*   src = (const int*)d_in[1];
    const int*   dst = (const int*)d_in[2];
    // d_in[3] = num_graphs (compile-time constant here)
    const float* W1a = (const float*)d_in[4];
    const float* b1a = (const float*)d_in[5];
    const float* W1b = (const float*)d_in[6];
    const float* b1b = (const float*)d_in[7];
    const float* g1  = (const float*)d_in[8];
    const float* be1 = (const float*)d_in[9];
    const float* W2a = (const float*)d_in[10];
    const float* b2a = (const float*)d_in[11];
    const float* W2b = (const float*)d_in[12];
    const float* b2b = (const float*)d_in[13];
    const float* g2  = (const float*)d_in[14];
    const float* be2 = (const float*)d_in[15];
    const float* W3a = (const float*)d_in[16];
    const float* b3a = (const float*)d_in[17];
    const float* W3b = (const float*)d_in[18];
    const float* b3b = (const float*)d_in[19];
    const float* g3  = (const float*)d_in[20];
    const float* be3 = (const float*)d_in[21];
    const float* Wfc = (const float*)d_in[22];
    const float* bfc = (const float*)d_in[23];
    float* out = (float*)d_out;

    const int TPB = 256;
    k_zero<<<(NNODES + TPB - 1) / TPB, TPB>>>();
    k_deg<<<(NEDGES + TPB - 1) / TPB, TPB>>>(dst);
    k_initagg1<<<(NNODES + TPB - 1) / TPB, TPB>>>(x);
    k_edge1<<<(NEDGES + TPB - 1) / TPB, TPB>>>(x, src, dst);

    // layer 1: input 4ch, no BN fold; write agg for layer 2
    k_mlp<4, false, true><<<NNODES / 64, TPB>>>(W1a, b1a, W1b, b1b, nullptr, nullptr, 0, 0);

    k_edge64<<<(NEDGES * 16 + TPB - 1) / TPB, TPB>>>(src, dst);
    // layer 2: fold BN1 into input
    k_mlp<64, true, true><<<NNODES / 64, TPB>>>(W2a, b2a, W2b, b2b, g1, be1, 0, 128);

    k_edge64<<<(NEDGES * 16 + TPB - 1) / TPB, TPB>>>(src, dst);
    // layer 3: fold BN2 into input; no agg write
    k_mlp<64, true, false><<<NNODES / 64, TPB>>>(W3a, b3a, W3b, b3b, g2, be2, 128, 256);

    // BN3 + pool + classifier
    k_final<<<NGRAPHS, 64>>>(g3, be3, Wfc, bfc, out);
}

// round 7
// speedup vs baseline: 1.3340x; 1.3340x over previous
#include <cuda_runtime.h>

#define NNODES 507904
#define NEDGES 4063232
#define HID 64
#define NGRAPHS 8192
#define NPG 62
#define BN_EPS 1e-5f
#define FN ((float)NNODES)
#define APAD 68
#define BKT_CAP 64

// -------- device scratch (no allocations allowed) --------
__device__ float g_hA[(size_t)NNODES * HID];       // activation buffer A
__device__ float g_hB[(size_t)NNODES * HID];       // activation buffer B
__device__ int   g_bkt[(size_t)NNODES * BKT_CAP];  // incoming-src bucket list per node
__device__ int   g_cur[NNODES];                    // bucket cursor == in-degree
__device__ float g_stat[6 * HID];                  // [sum0,sq0, sum1,sq1, sum2,sq2]

// packed fp32 FMA (Blackwell f32x2): d = a*b + d. Explicit mov.b64 pack/unpack —
// ptxas pairs the registers, movs are elided; avoids aliasing UB.
__device__ __forceinline__ void ffma2(float2& d, float2 a, float2 b) {
    asm("{\n\t"
        ".reg .b64 ra, rb, rd;\n\t"
        "mov.b64 ra, {%2, %3};\n\t"
        "mov.b64 rb, {%4, %5};\n\t"
        "mov.b64 rd, {%0, %1};\n\t"
        "fma.rn.f32x2 rd, ra, rb, rd;\n\t"
        "mov.b64 {%0, %1}, rd;\n\t"
        "}"
        : "+f"(d.x), "+f"(d.y)
        : "f"(a.x), "f"(a.y), "f"(b.x), "f"(b.y));
}

// -------- setup kernels --------
__global__ void k_zero() {
    int i = blockIdx.x * blockDim.x + threadIdx.x;
    if (i < NNODES) g_cur[i] = 0;
    if (i < 6 * HID) g_stat[i] = 0.f;
}

// build padded-CSR buckets: for each edge, append src to dst's bucket
__global__ void k_scatter(const int* __restrict__ src, const int* __restrict__ dst) {
    int e = blockIdx.x * blockDim.x + threadIdx.x;
    if (e < NEDGES) {
        int d = dst[e];
        int p = atomicAdd(&g_cur[d], 1);
        if (p < BKT_CAP) g_bkt[(size_t)d * BKT_CAP + p] = src[e];
    }
}

// -------- fused GIN layer: gather(+BN-fold) -> GEMM1 -> relu -> GEMM2 -> relu -> stats --------
// Block: 256 threads, 64 nodes. GEMM thread tile: 4 nodes x 4 channels.
// srcsel/dstsel pick between g_hA (0) and g_hB (1): double-buffered so the
// neighbor gather (reads prev layer) never races this layer's output writes.
template<int KIN, bool BNFOLD>
__global__ __launch_bounds__(256) void k_mlp(
    const float* __restrict__ xin, int srcsel, int dstsel,
    const float* __restrict__ Wa, const float* __restrict__ ba,
    const float* __restrict__ Wb, const float* __restrict__ bb,
    const float* __restrict__ gamma, const float* __restrict__ beta,
    int stat_in_off, int stat_out_off)
{
    __shared__ float sA[64 * APAD];
    __shared__ float sW[64 * 64];
    __shared__ float sBias[64];
    __shared__ float sS[64], sT[64];
    __shared__ float sStat[128];

    const int tid = threadIdx.x;
    const int nb = blockIdx.x * 64;
    const float* __restrict__ gsrc = srcsel ? g_hB : g_hA;
    float* __restrict__ gout = dstsel ? g_hB : g_hA;

    if (tid < 128) sStat[tid] = 0.f;
    if (BNFOLD && tid < 64) {
        float sum = g_stat[stat_in_off + tid];
        float sq  = g_stat[stat_in_off + 64 + tid];
        float mean = sum / FN;
        float var  = sq / FN - mean * mean;
        float inv  = rsqrtf(var + BN_EPS);
        float s    = gamma[tid] * inv;
        sS[tid] = s;
        sT[tid] = beta[tid] - mean * s;
    }
    if (tid < 64) sBias[tid] = ba[tid];
    for (int i = tid; i < KIN * 64; i += 256) sW[i] = Wa[i];
    __syncthreads();

    // ---- input phase: fused neighbor gather (+ BN fold) ----
    if (KIN == 4) {
        if (tid < 64) {
            int node = nb + tid;
            int deg = g_cur[node]; if (deg > BKT_CAP) deg = BKT_CAP;
            float4 a = ((const float4*)xin)[node];
            const int* bkt = g_bkt + (size_t)node * BKT_CAP;
            for (int j = 0; j < deg; j++) {
                float4 v = ((const float4*)xin)[bkt[j]];
                a.x += v.x; a.y += v.y; a.z += v.z; a.w += v.w;
            }
            *(float4*)&sA[tid * APAD] = a;
        }
    } else {
        int m = tid >> 2, c4 = tid & 3;
        int node = nb + m;
        int deg = g_cur[node]; if (deg > BKT_CAP) deg = BKT_CAP;
        const float* own = gsrc + (size_t)node * 64 + c4 * 16;
        float4 a0 = *(const float4*)(own);
        float4 a1 = *(const float4*)(own + 4);
        float4 a2 = *(const float4*)(own + 8);
        float4 a3 = *(const float4*)(own + 12);
        const int* bkt = g_bkt + (size_t)node * BKT_CAP;
        for (int j = 0; j < deg; j++) {
            const float* r = gsrc + (size_t)bkt[j] * 64 + c4 * 16;
            float4 v0 = *(const float4*)(r);
            float4 v1 = *(const float4*)(r + 4);
            float4 v2 = *(const float4*)(r + 8);
            float4 v3 = *(const float4*)(r + 12);
            a0.x += v0.x; a0.y += v0.y; a0.z += v0.z; a0.w += v0.w;
            a1.x += v1.x; a1.y += v1.y; a1.z += v1.z; a1.w += v1.w;
            a2.x += v2.x; a2.y += v2.y; a2.z += v2.z; a2.w += v2.w;
            a3.x += v3.x; a3.y += v3.y; a3.z += v3.z; a3.w += v3.w;
        }
        int cb = c4 * 16;
        float fd = 1.f + (float)deg;
        float va[16];
        *(float4*)&va[0]  = a0;
        *(float4*)&va[4]  = a1;
        *(float4*)&va[8]  = a2;
        *(float4*)&va[12] = a3;
        #pragma unroll
        for (int qq = 0; qq < 4; qq++) {
            float4 w;
            int ch = cb + qq * 4;
            if (BNFOLD) {
                w.x = sS[ch + 0] * va[qq * 4 + 0] + fd * sT[ch + 0];
                w.y = sS[ch + 1] * va[qq * 4 + 1] + fd * sT[ch + 1];
                w.z = sS[ch + 2] * va[qq * 4 + 2] + fd * sT[ch + 2];
                w.w = sS[ch + 3] * va[qq * 4 + 3] + fd * sT[ch + 3];
            } else {
                w.x = va[qq * 4 + 0]; w.y = va[qq * 4 + 1];
                w.z = va[qq * 4 + 2]; w.w = va[qq * 4 + 3];
            }
            *(float4*)&sA[m * APAD + ch] = w;
        }
    }
    __syncthreads();

    const int mt = tid >> 4;   // 0..15
    const int nt = tid & 15;   // 0..15

    float2 acc[4][2];
    #pragma unroll
    for (int i = 0; i < 4; i++) { acc[i][0] = make_float2(0.f, 0.f); acc[i][1] = make_float2(0.f, 0.f); }

    // GEMM1: [64 x KIN] @ [KIN x 64]
    #pragma unroll 4
    for (int k = 0; k < KIN; k++) {
        float a0 = sA[(mt * 4 + 0) * APAD + k];
        float a1 = sA[(mt * 4 + 1) * APAD + k];
        float a2 = sA[(mt * 4 + 2) * APAD + k];
        float a3 = sA[(mt * 4 + 3) * APAD + k];
        float4 b = *(const float4*)&sW[k * 64 + nt * 4];
        float2 b01 = make_float2(b.x, b.y), b23 = make_float2(b.z, b.w);
        ffma2(acc[0][0], make_float2(a0, a0), b01); ffma2(acc[0][1], make_float2(a0, a0), b23);
        ffma2(acc[1][0], make_float2(a1, a1), b01); ffma2(acc[1][1], make_float2(a1, a1), b23);
        ffma2(acc[2][0], make_float2(a2, a2), b01); ffma2(acc[2][1], make_float2(a2, a2), b23);
        ffma2(acc[3][0], make_float2(a3, a3), b01); ffma2(acc[3][1], make_float2(a3, a3), b23);
    }

    float bj0 = sBias[nt * 4 + 0];
    float bj1 = sBias[nt * 4 + 1];
    float bj2 = sBias[nt * 4 + 2];
    float bj3 = sBias[nt * 4 + 3];
    __syncthreads();   // done reading sA / sBias

    // mid = relu(acc + b1) -> back into sA; reload W2/b2
    #pragma unroll
    for (int i = 0; i < 4; i++) {
        float4 v;
        v.x = fmaxf(acc[i][0].x + bj0, 0.f);
        v.y = fmaxf(acc[i][0].y + bj1, 0.f);
        v.z = fmaxf(acc[i][1].x + bj2, 0.f);
        v.w = fmaxf(acc[i][1].y + bj3, 0.f);
        *(float4*)&sA[(mt * 4 + i) * APAD + nt * 4] = v;
    }
    for (int i = tid; i < 64 * 64; i += 256) sW[i] = Wb[i];
    if (tid < 64) sBias[tid] = bb[tid];
    __syncthreads();

    #pragma unroll
    for (int i = 0; i < 4; i++) { acc[i][0] = make_float2(0.f, 0.f); acc[i][1] = make_float2(0.f, 0.f); }

    // GEMM2: [64 x 64] @ [64 x 64]
    #pragma unroll 4
    for (int k = 0; k < 64; k++) {
        float a0 = sA[(mt * 4 + 0) * APAD + k];
        float a1 = sA[(mt * 4 + 1) * APAD + k];
        float a2 = sA[(mt * 4 + 2) * APAD + k];
        float a3 = sA[(mt * 4 + 3) * APAD + k];
        float4 b = *(const float4*)&sW[k * 64 + nt * 4];
        float2 b01 = make_float2(b.x, b.y), b23 = make_float2(b.z, b.w);
        ffma2(acc[0][0], make_float2(a0, a0), b01); ffma2(acc[0][1], make_float2(a0, a0), b23);
        ffma2(acc[1][0], make_float2(a1, a1), b01); ffma2(acc[1][1], make_float2(a1, a1), b23);
        ffma2(acc[2][0], make_float2(a2, a2), b01); ffma2(acc[2][1], make_float2(a2, a2), b23);
        ffma2(acc[3][0], make_float2(a3, a3), b01); ffma2(acc[3][1], make_float2(a3, a3), b23);
    }

    float cj0 = sBias[nt * 4 + 0];
    float cj1 = sBias[nt * 4 + 1];
    float cj2 = sBias[nt * 4 + 2];
    float cj3 = sBias[nt * 4 + 3];

    float psum[4] = {0.f, 0.f, 0.f, 0.f};
    float psq[4]  = {0.f, 0.f, 0.f, 0.f};

    #pragma unroll
    for (int i = 0; i < 4; i++) {
        float4 v;
        v.x = fmaxf(acc[i][0].x + cj0, 0.f);
        v.y = fmaxf(acc[i][0].y + cj1, 0.f);
        v.z = fmaxf(acc[i][1].x + cj2, 0.f);
        v.w = fmaxf(acc[i][1].y + cj3, 0.f);
        size_t row = (size_t)(nb + mt * 4 + i) * 64 + (size_t)nt * 4;
        *(float4*)&gout[row] = v;
        psum[0] += v.x; psq[0] += v.x * v.x;
        psum[1] += v.y; psq[1] += v.y * v.y;
        psum[2] += v.z; psq[2] += v.z * v.z;
        psum[3] += v.w; psq[3] += v.w * v.w;
    }

    // reduce lane l <-> l^16 (same nt, adjacent mt), then shared atomics
    #pragma unroll
    for (int j = 0; j < 4; j++) {
        psum[j] += __shfl_xor_sync(0xffffffffu, psum[j], 16);
        psq[j]  += __shfl_xor_sync(0xffffffffu, psq[j], 16);
    }
    if ((tid & 16) == 0) {
        #pragma unroll
        for (int j = 0; j < 4; j++) {
            atomicAdd(&sStat[nt * 4 + j], psum[j]);
            atomicAdd(&sStat[64 + nt * 4 + j], psq[j]);
        }
    }
    __syncthreads();
    if (tid < 128) atomicAdd(&g_stat[stat_out_off + tid], sStat[tid]);
}

// -------- final: BN3 + per-graph sum-pool + fc (reads g_hA = layer-3 output) --------
__global__ __launch_bounds__(64) void k_final(
    const float* __restrict__ g3, const float* __restrict__ be3,
    const float* __restrict__ Wfc, const float* __restrict__ bfc,
    float* __restrict__ out)
{
    int g = blockIdx.x;
    int c = threadIdx.x;  // 0..63

    float sum = g_stat[4 * 64 + c];
    float sq  = g_stat[5 * 64 + c];
    float mean = sum / FN;
    float var  = sq / FN - mean * mean;
    float inv  = rsqrtf(var + BN_EPS);
    float s    = g3[c] * inv;
    float t    = be3[c] - mean * s;

    const float* base = g_hA + (size_t)g * NPG * 64;
    float acc = 0.f;
    #pragma unroll 2
    for (int i = 0; i < NPG; i++) acc += base[(size_t)i * 64 + c];
    float pool = s * acc + (float)NPG * t;

    __shared__ float red[3][64];
    red[0][c] = pool * Wfc[c * 3 + 0];
    red[1][c] = pool * Wfc[c * 3 + 1];
    red[2][c] = pool * Wfc[c * 3 + 2];
    __syncthreads();
    if (c < 3) {
        float a = 0.f;
        #pragma unroll
        for (int i = 0; i < 64; i++) a += red[c][i];
        out[(size_t)g * 3 + c] = a + bfc[c];
    }
}

// -------- launch --------
extern "C" void kernel_launch(void* const* d_in, const int* in_sizes, int n_in,
                              void* d_out, int out_size) {
    (void)in_sizes; (void)n_in; (void)out_size;
    const float* x   = (const float*)d_in[0];
    const int*   src = (const int*)d_in[1];
    const int*   dst = (const int*)d_in[2];
    // d_in[3] = num_graphs (compile-time constant here)
    const float* W1a = (const float*)d_in[4];
    const float* b1a = (const float*)d_in[5];
    const float* W1b = (const float*)d_in[6];
    const float* b1b = (const float*)d_in[7];
    const float* g1  = (const float*)d_in[8];
    const float* be1 = (const float*)d_in[9];
    const float* W2a = (const float*)d_in[10];
    const float* b2a = (const float*)d_in[11];
    const float* W2b = (const float*)d_in[12];
    const float* b2b = (const float*)d_in[13];
    const float* g2  = (const float*)d_in[14];
    const float* be2 = (const float*)d_in[15];
    const float* W3a = (const float*)d_in[16];
    const float* b3a = (const float*)d_in[17];
    const float* W3b = (const float*)d_in[18];
    const float* b3b = (const float*)d_in[19];
    const float* g3  = (const float*)d_in[20];
    const float* be3 = (const float*)d_in[21];
    const float* Wfc = (const float*)d_in[22];
    const float* bfc = (const float*)d_in[23];
    float* out = (float*)d_out;

    const int TPB = 256;
    k_zero<<<(NNODES + TPB - 1) / TPB, TPB>>>();
    k_scatter<<<(NEDGES + TPB - 1) / TPB, TPB>>>(src, dst);

    // layer 1: input x (4ch), gather fused, no BN fold -> writes A
    k_mlp<4, false><<<NNODES / 64, TPB>>>(x, 0, 0, W1a, b1a, W1b, b1b, nullptr, nullptr, 0, 0);
    // layer 2: gather from A + fold BN1 -> writes B
    k_mlp<64, true><<<NNODES / 64, TPB>>>(nullptr, 0, 1, W2a, b2a, W2b, b2b, g1, be1, 0, 128);
    // layer 3: gather from B + fold BN2 -> writes A
    k_mlp<64, true><<<NNODES / 64, TPB>>>(nullptr, 1, 0, W3a, b3a, W3b, b3b, g2, be2, 128, 256);

    // BN3 + pool + classifier (reads A)
    k_final<<<NGRAPHS, 64>>>(g3, be3, Wfc, bfc, out);
}

// round 9
// speedup vs baseline: 1.4561x; 1.0916x over previous
#include <cuda_runtime.h>

#define NNODES 507904
#define NEDGES 4063232
#define HID 64
#define NGRAPHS 8192
#define NPG 62
#define BN_EPS 1e-5f
#define FN ((float)NNODES)
#define BKT_CAP 64
#define MTILE 128

// dynamic smem layout (floats): sAT[8192] | sW[4096] | sBias[64] | sS[64] | sT[64] | sStat[128]
#define SMEM_FLOATS (8192 + 4096 + 64 + 64 + 64 + 128)
#define SMEM_BYTES  (SMEM_FLOATS * 4)

// -------- device scratch (no allocations allowed) --------
__device__ float g_hA[(size_t)NNODES * HID];       // activation buffer A
__device__ float g_hB[(size_t)NNODES * HID];       // activation buffer B
__device__ int   g_bkt[(size_t)NNODES * BKT_CAP];  // incoming-src bucket list per node
__device__ int   g_cur[NNODES];                    // bucket cursor == in-degree
__device__ float g_stat[6 * HID];                  // [sum0,sq0, sum1,sq1, sum2,sq2]

// packed fp32 FMA (Blackwell f32x2): d = a*b + d
__device__ __forceinline__ void ffma2(float2& d, float2 a, float2 b) {
    asm("{\n\t"
        ".reg .b64 ra, rb, rd;\n\t"
        "mov.b64 ra, {%2, %3};\n\t"
        "mov.b64 rb, {%4, %5};\n\t"
        "mov.b64 rd, {%0, %1};\n\t"
        "fma.rn.f32x2 rd, ra, rb, rd;\n\t"
        "mov.b64 {%0, %1}, rd;\n\t"
        "}"
        : "+f"(d.x), "+f"(d.y)
        : "f"(a.x), "f"(a.y), "f"(b.x), "f"(b.y));
}

// -------- setup kernels --------
__global__ void k_zero() {
    int i = blockIdx.x * blockDim.x + threadIdx.x;
    if (i < NNODES) g_cur[i] = 0;
    if (i < 6 * HID) g_stat[i] = 0.f;
}

__global__ void k_scatter(const int* __restrict__ src, const int* __restrict__ dst) {
    int e = blockIdx.x * blockDim.x + threadIdx.x;
    if (e < NEDGES) {
        int d = dst[e];
        int p = atomicAdd(&g_cur[d], 1);
        if (p < BKT_CAP) g_bkt[(size_t)d * BKT_CAP + p] = src[e];
    }
}

// -------- fused GIN layer --------
// 128 threads, 128 nodes/CTA. GEMM thread tile: 8 nodes x 8 channels.
// sAT: transposed A [k][m], XOR-swizzled:
//   float offset(k,m) = k*128 + ((((m>>2) ^ ((k>>3)&7)) << 2) | (m&3))
// sW: [k][n] with float4-group permutation p(j) = (j>>1)|((j&1)<<3) so the two
//   B LDS.128s per thread hit phys groups nt and nt+8 (8 distinct bank-groups).
template<int KIN, bool BNFOLD>
__global__ __launch_bounds__(128, 4) void k_mlp(
    const float* __restrict__ xin, int srcsel, int dstsel,
    const float* __restrict__ Wa, const float* __restrict__ ba,
    const float* __restrict__ Wb, const float* __restrict__ bb,
    const float* __restrict__ gamma, const float* __restrict__ beta,
    int stat_in_off, int stat_out_off)
{
    extern __shared__ float smem[];
    float* sAT   = smem;                 // 8192 floats (32 KB)
    float* sW    = smem + 8192;          // 4096 floats (16 KB)
    float* sBias = smem + 8192 + 4096;   // 64
    float* sS    = sBias + 64;           // 64
    float* sT    = sS + 64;              // 64
    float* sStat = sT + 64;              // 128

    const int tid = threadIdx.x;
    const int nb = blockIdx.x * MTILE;
    const float* __restrict__ gsrc = srcsel ? g_hB : g_hA;
    float* __restrict__ gout = dstsel ? g_hB : g_hA;

    sStat[tid] = 0.f;
    if (BNFOLD && tid < 64) {
        float sum = g_stat[stat_in_off + tid];
        float sq  = g_stat[stat_in_off + 64 + tid];
        float mean = sum / FN;
        float var  = sq / FN - mean * mean;
        float inv  = rsqrtf(var + BN_EPS);
        float s    = gamma[tid] * inv;
        sS[tid] = s;
        sT[tid] = beta[tid] - mean * s;
    }
    if (tid < 64) sBias[tid] = ba[tid];
    // load Wa with n-group permutation
    for (int i = tid; i < KIN * 64; i += 128) {
        int k = i >> 6, n = i & 63;
        int j = n >> 2;
        int p = (j >> 1) | ((j & 1) << 3);
        sW[k * 64 + p * 4 + (n & 3)] = Wa[i];
    }
    __syncthreads();

    // ---- gather phase: neighbor sum (+BN fold) -> sAT (transposed, swizzled) ----
    if (KIN == 4) {
        int m = tid;
        int node = nb + m;
        int deg = g_cur[node]; if (deg > BKT_CAP) deg = BKT_CAP;
        float4 a = ((const float4*)xin)[node];
        const int* bkt = g_bkt + (size_t)node * BKT_CAP;
        for (int j = 0; j < deg; j++) {
            float4 v = ((const float4*)xin)[bkt[j]];
            a.x += v.x; a.y += v.y; a.z += v.z; a.w += v.w;
        }
        int base = ((m >> 2) << 2) | (m & 3);   // k<8 -> swz=0
        sAT[0 * 128 + base] = a.x;
        sAT[1 * 128 + base] = a.y;
        sAT[2 * 128 + base] = a.z;
        sAT[3 * 128 + base] = a.w;
    } else {
        const int chunk = tid & 15;   // float4 chunk of row: channels chunk*4..+3
        const int mloc  = tid >> 4;   // 0..7
        float4 sSv, sTv;
        if (BNFOLD) {
            sSv = *(const float4*)&sS[chunk * 4];
            sTv = *(const float4*)&sT[chunk * 4];
        }
        #pragma unroll 1
        for (int pass = 0; pass < 16; pass++) {
            int m = pass * 8 + mloc;
            int node = nb + m;
            int deg = g_cur[node]; if (deg > BKT_CAP) deg = BKT_CAP;
            float4 a = ((const float4*)(gsrc + (size_t)node * 64))[chunk];
            const int* bkt = g_bkt + (size_t)node * BKT_CAP;
            for (int j = 0; j < deg; j++) {
                float4 v = ((const float4*)(gsrc + (size_t)bkt[j] * 64))[chunk];
                a.x += v.x; a.y += v.y; a.z += v.z; a.w += v.w;
            }
            if (BNFOLD) {
                float fd = 1.f + (float)deg;
                a.x = sSv.x * a.x + fd * sTv.x;
                a.y = sSv.y * a.y + fd * sTv.y;
                a.z = sSv.z * a.z + fd * sTv.z;
                a.w = sSv.w * a.w + fd * sTv.w;
            }
            int mg = m >> 2, mr = m & 3;
            #pragma unroll
            for (int l = 0; l < 4; l++) {
                int k = chunk * 4 + l;
                int g = mg ^ ((k >> 3) & 7);
                sAT[k * 128 + (g << 2) + mr] = (&a.x)[l];
            }
        }
    }
    __syncthreads();

    const int mt = tid >> 3;   // 0..15, m_base = mt*8
    const int nt = tid & 7;    // 0..7,  n_base = nt*8

    float2 acc[8][4];
    #pragma unroll
    for (int i = 0; i < 8; i++)
        #pragma unroll
        for (int jj = 0; jj < 4; jj++) acc[i][jj] = make_float2(0.f, 0.f);

    // ---- GEMM1: [128 x KIN] @ [KIN x 64] ----
    #pragma unroll 4
    for (int k = 0; k < KIN; k++) {
        int swz = (k >> 3) & 7;
        float4 aA = *(const float4*)&sAT[k * 128 + (((2 * mt    ) ^ swz) << 2)];
        float4 aB = *(const float4*)&sAT[k * 128 + (((2 * mt + 1) ^ swz) << 2)];
        float4 bA = *(const float4*)&sW[k * 64 + nt * 4];
        float4 bB = *(const float4*)&sW[k * 64 + (nt + 8) * 4];
        float2 b0 = make_float2(bA.x, bA.y), b1 = make_float2(bA.z, bA.w);
        float2 b2 = make_float2(bB.x, bB.y), b3 = make_float2(bB.z, bB.w);
        float am[8] = {aA.x, aA.y, aA.z, aA.w, aB.x, aB.y, aB.z, aB.w};
        #pragma unroll
        for (int i = 0; i < 8; i++) {
            float2 ai = make_float2(am[i], am[i]);
            ffma2(acc[i][0], ai, b0);
            ffma2(acc[i][1], ai, b1);
            ffma2(acc[i][2], ai, b2);
            ffma2(acc[i][3], ai, b3);
        }
    }

    float bj[8];
    #pragma unroll
    for (int j = 0; j < 8; j++) bj[j] = sBias[nt * 8 + j];
    __syncthreads();   // done reading sAT / sW / sBias

    // ---- mid: relu(acc + b1) -> sAT (k = mid channel); reload W2/b2 ----
    #pragma unroll
    for (int j = 0; j < 8; j++) {
        int k2 = nt * 8 + j;
        int jj = j >> 1;
        float v0, v1, v2, v3, v4, v5, v6, v7;
        if (j & 1) {
            v0 = acc[0][jj].y; v1 = acc[1][jj].y; v2 = acc[2][jj].y; v3 = acc[3][jj].y;
            v4 = acc[4][jj].y; v5 = acc[5][jj].y; v6 = acc[6][jj].y; v7 = acc[7][jj].y;
        } else {
            v0 = acc[0][jj].x; v1 = acc[1][jj].x; v2 = acc[2][jj].x; v3 = acc[3][jj].x;
            v4 = acc[4][jj].x; v5 = acc[5][jj].x; v6 = acc[6][jj].x; v7 = acc[7][jj].x;
        }
        float b = bj[j];
        float4 lo = make_float4(fmaxf(v0 + b, 0.f), fmaxf(v1 + b, 0.f),
                                fmaxf(v2 + b, 0.f), fmaxf(v3 + b, 0.f));
        float4 hi = make_float4(fmaxf(v4 + b, 0.f), fmaxf(v5 + b, 0.f),
                                fmaxf(v6 + b, 0.f), fmaxf(v7 + b, 0.f));
        // (k2>>3)&7 == nt
        *(float4*)&sAT[k2 * 128 + (((2 * mt    ) ^ nt) << 2)] = lo;
        *(float4*)&sAT[k2 * 128 + (((2 * mt + 1) ^ nt) << 2)] = hi;
    }
    for (int i = tid; i < 64 * 64; i += 128) {
        int k = i >> 6, n = i & 63;
        int j = n >> 2;
        int p = (j >> 1) | ((j & 1) << 3);
        sW[k * 64 + p * 4 + (n & 3)] = Wb[i];
    }
    if (tid < 64) sBias[tid] = bb[tid];
    __syncthreads();

    #pragma unroll
    for (int i = 0; i < 8; i++)
        #pragma unroll
        for (int jj = 0; jj < 4; jj++) acc[i][jj] = make_float2(0.f, 0.f);

    // ---- GEMM2: [128 x 64] @ [64 x 64] ----
    #pragma unroll 4
    for (int k = 0; k < 64; k++) {
        int swz = (k >> 3) & 7;
        float4 aA = *(const float4*)&sAT[k * 128 + (((2 * mt    ) ^ swz) << 2)];
        float4 aB = *(const float4*)&sAT[k * 128 + (((2 * mt + 1) ^ swz) << 2)];
        float4 bA = *(const float4*)&sW[k * 64 + nt * 4];
        float4 bB = *(const float4*)&sW[k * 64 + (nt + 8) * 4];
        float2 b0 = make_float2(bA.x, bA.y), b1 = make_float2(bA.z, bA.w);
        float2 b2 = make_float2(bB.x, bB.y), b3 = make_float2(bB.z, bB.w);
        float am[8] = {aA.x, aA.y, aA.z, aA.w, aB.x, aB.y, aB.z, aB.w};
        #pragma unroll
        for (int i = 0; i < 8; i++) {
            float2 ai = make_float2(am[i], am[i]);
            ffma2(acc[i][0], ai, b0);
            ffma2(acc[i][1], ai, b1);
            ffma2(acc[i][2], ai, b2);
            ffma2(acc[i][3], ai, b3);
        }
    }

    float cj[8];
    #pragma unroll
    for (int j = 0; j < 8; j++) cj[j] = sBias[nt * 8 + j];

    // ---- epilogue: relu + store + BN stats ----
    float psum[8], psq[8];
    #pragma unroll
    for (int j = 0; j < 8; j++) { psum[j] = 0.f; psq[j] = 0.f; }

    #pragma unroll
    for (int i = 0; i < 8; i++) {
        float4 lo, hi;
        lo.x = fmaxf(acc[i][0].x + cj[0], 0.f);
        lo.y = fmaxf(acc[i][0].y + cj[1], 0.f);
        lo.z = fmaxf(acc[i][1].x + cj[2], 0.f);
        lo.w = fmaxf(acc[i][1].y + cj[3], 0.f);
        hi.x = fmaxf(acc[i][2].x + cj[4], 0.f);
        hi.y = fmaxf(acc[i][2].y + cj[5], 0.f);
        hi.z = fmaxf(acc[i][3].x + cj[6], 0.f);
        hi.w = fmaxf(acc[i][3].y + cj[7], 0.f);
        size_t row = (size_t)(nb + mt * 8 + i) * 64 + (size_t)nt * 8;
        *(float4*)&gout[row]     = lo;
        *(float4*)&gout[row + 4] = hi;
        psum[0] += lo.x; psq[0] += lo.x * lo.x;
        psum[1] += lo.y; psq[1] += lo.y * lo.y;
        psum[2] += lo.z; psq[2] += lo.z * lo.z;
        psum[3] += lo.w; psq[3] += lo.w * lo.w;
        psum[4] += hi.x; psq[4] += hi.x * hi.x;
        psum[5] += hi.y; psq[5] += hi.y * hi.y;
        psum[6] += hi.z; psq[6] += hi.z * hi.z;
        psum[7] += hi.w; psq[7] += hi.w * hi.w;
    }

    // reduce over mt within warp (tid bits 3,4), then shared atomics
    #pragma unroll
    for (int j = 0; j < 8; j++) {
        psum[j] += __shfl_xor_sync(0xffffffffu, psum[j], 8);
        psq[j]  += __shfl_xor_sync(0xffffffffu, psq[j], 8);
        psum[j] += __shfl_xor_sync(0xffffffffu, psum[j], 16);
        psq[j]  += __shfl_xor_sync(0xffffffffu, psq[j], 16);
    }
    if ((tid & 24) == 0) {
        #pragma unroll
        for (int j = 0; j < 8; j++) {
            atomicAdd(&sStat[nt * 8 + j], psum[j]);
            atomicAdd(&sStat[64 + nt * 8 + j], psq[j]);
        }
    }
    __syncthreads();
    atomicAdd(&g_stat[stat_out_off + tid], sStat[tid]);
}

// -------- final: BN3 + per-graph sum-pool + fc (reads g_hA) --------
__global__ __launch_bounds__(64) void k_final(
    const float* __restrict__ g3, const float* __restrict__ be3,
    const float* __restrict__ Wfc, const float* __restrict__ bfc,
    float* __restrict__ out)
{
    int g = blockIdx.x;
    int c = threadIdx.x;  // 0..63

    float sum = g_stat[4 * 64 + c];
    float sq  = g_stat[5 * 64 + c];
    float mean = sum / FN;
    float var  = sq / FN - mean * mean;
    float inv  = rsqrtf(var + BN_EPS);
    float s    = g3[c] * inv;
    float t    = be3[c] - mean * s;

    const float* base = g_hA + (size_t)g * NPG * 64;
    float acc = 0.f;
    #pragma unroll 2
    for (int i = 0; i < NPG; i++) acc += base[(size_t)i * 64 + c];
    float pool = s * acc + (float)NPG * t;

    __shared__ float red[3][64];
    red[0][c] = pool * Wfc[c * 3 + 0];
    red[1][c] = pool * Wfc[c * 3 + 1];
    red[2][c] = pool * Wfc[c * 3 + 2];
    __syncthreads();
    if (c < 3) {
        float a = 0.f;
        #pragma unroll
        for (int i = 0; i < 64; i++) a += red[c][i];
        out[(size_t)g * 3 + c] = a + bfc[c];
    }
}

// -------- launch --------
extern "C" void kernel_launch(void* const* d_in, const int* in_sizes, int n_in,
                              void* d_out, int out_size) {
    (void)in_sizes; (void)n_in; (void)out_size;
    const float* x   = (const float*)d_in[0];
    const int*   src = (const int*)d_in[1];
    const int*   dst = (const int*)d_in[2];
    const float* W1a = (const float*)d_in[4];
    const float* b1a = (const float*)d_in[5];
    const float* W1b = (const float*)d_in[6];
    const float* b1b = (const float*)d_in[7];
    const float* g1  = (const float*)d_in[8];
    const float* be1 = (const float*)d_in[9];
    const float* W2a = (const float*)d_in[10];
    const float* b2a = (const float*)d_in[11];
    const float* W2b = (const float*)d_in[12];
    const float* b2b = (const float*)d_in[13];
    const float* g2  = (const float*)d_in[14];
    const float* be2 = (const float*)d_in[15];
    const float* W3a = (const float*)d_in[16];
    const float* b3a = (const float*)d_in[17];
    const float* W3b = (const float*)d_in[18];
    const float* b3b = (const float*)d_in[19];
    const float* g3  = (const float*)d_in[20];
    const float* be3 = (const float*)d_in[21];
    const float* Wfc = (const float*)d_in[22];
    const float* bfc = (const float*)d_in[23];
    float* out = (float*)d_out;

    // opt-in smem (host attribute set, not a stream op — capture-safe, idempotent)
    cudaFuncSetAttribute(k_mlp<4, false>, cudaFuncAttributeMaxDynamicSharedMemorySize, SMEM_BYTES);
    cudaFuncSetAttribute(k_mlp<64, true>, cudaFuncAttributeMaxDynamicSharedMemorySize, SMEM_BYTES);

    const int TPB = 256;
    k_zero<<<(NNODES + TPB - 1) / TPB, TPB>>>();
    k_scatter<<<(NEDGES + TPB - 1) / TPB, TPB>>>(src, dst);

    // layer 1: input x (4ch) -> writes A
    k_mlp<4, false><<<NNODES / MTILE, 128, SMEM_BYTES>>>(x, 0, 0, W1a, b1a, W1b, b1b, nullptr, nullptr, 0, 0);
    // layer 2: gather from A + fold BN1 -> writes B
    k_mlp<64, true><<<NNODES / MTILE, 128, SMEM_BYTES>>>(nullptr, 0, 1, W2a, b2a, W2b, b2b, g1, be1, 0, 128);
    // layer 3: gather from B + fold BN2 -> writes A
    k_mlp<64, true><<<NNODES / MTILE, 128, SMEM_BYTES>>>(nullptr, 1, 0, W3a, b3a, W3b, b3b, g2, be2, 128, 256);

    // BN3 + pool + classifier (reads A)
    k_final<<<NGRAPHS, 64>>>(g3, be3, Wfc, bfc, out);
}

// round 11
// speedup vs baseline: 1.8336x; 1.2592x over previous
#include <cuda_runtime.h>

#define NNODES 507904
#define NEDGES 4063232
#define HID 64
#define NGRAPHS 8192
#define NPG 62
#define BN_EPS 1e-5f
#define FN ((float)NNODES)
#define BKT_CAP 64
#define MTILE 128

// dynamic smem (floats):
// sAT[8192] | sW[4096] | sBias[64] | sS[64] | sT[64] | sStat[128]  = 12608 floats
#define SMEM_FLOATS (8192 + 4096 + 64 + 64 + 64 + 128)
#define SMEM_BYTES  (SMEM_FLOATS * 4)

// -------- device scratch (no allocations allowed) --------
__device__ float g_hA[(size_t)NNODES * HID];        // activation buffer A
__device__ float g_hB[(size_t)NNODES * HID];        // activation buffer B
__device__ int4  g_bkt4[(size_t)NNODES * (BKT_CAP / 4)];  // bucket lists (16B aligned)
__device__ int   g_cur[NNODES];                     // bucket cursor == in-degree
__device__ float g_stat[6 * HID];                   // [sum0,sq0, sum1,sq1, sum2,sq2]

// packed fp32 FMA (Blackwell f32x2): d = a*b + d
__device__ __forceinline__ void ffma2(float2& d, float2 a, float2 b) {
    asm("{\n\t"
        ".reg .b64 ra, rb, rd;\n\t"
        "mov.b64 ra, {%2, %3};\n\t"
        "mov.b64 rb, {%4, %5};\n\t"
        "mov.b64 rd, {%0, %1};\n\t"
        "fma.rn.f32x2 rd, ra, rb, rd;\n\t"
        "mov.b64 {%0, %1}, rd;\n\t"
        "}"
        : "+f"(d.x), "+f"(d.y)
        : "f"(a.x), "f"(a.y), "f"(b.x), "f"(b.y));
}

// -------- setup kernels --------
__global__ void k_zero() {
    int i = blockIdx.x * blockDim.x + threadIdx.x;
    if (i < NNODES) g_cur[i] = 0;
    if (i < 6 * HID) g_stat[i] = 0.f;
}

__global__ void k_scatter(const int* __restrict__ src, const int* __restrict__ dst) {
    int e = blockIdx.x * blockDim.x + threadIdx.x;
    if (e < NEDGES) {
        int d = dst[e];
        int p = atomicAdd(&g_cur[d], 1);
        if (p < BKT_CAP) ((int*)g_bkt4)[(size_t)d * BKT_CAP + p] = src[e];
    }
}

// -------- fused GIN layer --------
// 256 threads, 128 nodes/CTA. GEMM thread tile: 8 nodes x 4 channels.
// sAT: transposed A [k][m] fp32, XOR-swizzled:
//   float offset(k,m) = k*128 + ((((m>>2) ^ ((k>>3)&7)) << 2) | (m&3))
// sW: fp32 [k][n] straight layout — per-warp B-load is 16 consecutive float4s
//   (256B span, conflict-free, 2-lane broadcast).
template<int KIN, bool BNFOLD>
__global__ __launch_bounds__(256, 4) void k_mlp(
    const float* __restrict__ xin, int srcsel, int dstsel,
    const float* __restrict__ Wa, const float* __restrict__ ba,
    const float* __restrict__ Wb, const float* __restrict__ bb,
    const float* __restrict__ gamma, const float* __restrict__ beta,
    int stat_in_off, int stat_out_off)
{
    extern __shared__ float smem[];
    float* sAT   = smem;                 // 8192 floats (32 KB)
    float* sW    = smem + 8192;          // 4096 floats (16 KB)
    float* sBias = smem + 8192 + 4096;   // 64
    float* sS    = sBias + 64;           // 64
    float* sT    = sS + 64;              // 64
    float* sStat = sT + 64;              // 128

    const int tid = threadIdx.x;
    const int nb = blockIdx.x * MTILE;
    const float* __restrict__ gsrc = srcsel ? g_hB : g_hA;
    float* __restrict__ gout = dstsel ? g_hB : g_hA;

    if (tid < 128) sStat[tid] = 0.f;
    if (BNFOLD && tid < 64) {
        float sum = g_stat[stat_in_off + tid];
        float sq  = g_stat[stat_in_off + 64 + tid];
        float mean = sum / FN;
        float var  = sq / FN - mean * mean;
        float inv  = rsqrtf(var + BN_EPS);
        float s    = gamma[tid] * inv;
        sS[tid] = s;
        sT[tid] = beta[tid] - mean * s;
    }
    if (tid < 64) sBias[tid] = ba[tid];
    for (int i = tid; i < KIN * 64; i += 256) sW[i] = Wa[i];
    __syncthreads();

    // ---- gather phase: neighbor sum (+BN fold) -> sAT (transposed, swizzled) ----
    if (KIN == 4) {
        if (tid < 128) {
            int m = tid;
            int node = nb + m;
            int deg = g_cur[node]; if (deg > BKT_CAP) deg = BKT_CAP;
            const int4* bq = &g_bkt4[(size_t)node * (BKT_CAP / 4)];
            int4 q0 = bq[0], q1 = bq[1], q2 = bq[2], q3 = bq[3];
            int idx[16] = {q0.x, q0.y, q0.z, q0.w, q1.x, q1.y, q1.z, q1.w,
                           q2.x, q2.y, q2.z, q2.w, q3.x, q3.y, q3.z, q3.w};
            float4 a = ((const float4*)xin)[node];
            int jm = deg < 16 ? deg : 16;
            #pragma unroll
            for (int j = 0; j < 16; j++) {
                if (j < jm) {
                    float4 v = ((const float4*)xin)[idx[j]];
                    a.x += v.x; a.y += v.y; a.z += v.z; a.w += v.w;
                }
            }
            for (int j = 16; j < deg; j++) {
                float4 v = ((const float4*)xin)[((const int*)bq)[j]];
                a.x += v.x; a.y += v.y; a.z += v.z; a.w += v.w;
            }
            int base = ((m >> 2) << 2) | (m & 3);   // k<8 -> swz=0
            sAT[0 * 128 + base] = a.x;
            sAT[1 * 128 + base] = a.y;
            sAT[2 * 128 + base] = a.z;
            sAT[3 * 128 + base] = a.w;
        }
    } else {
        const int chunk = tid & 15;   // float4 chunk: channels chunk*4..+3
        const int mloc  = tid >> 4;   // 0..15
        float4 sSv, sTv;
        if (BNFOLD) {
            sSv = *(const float4*)&sS[chunk * 4];
            sTv = *(const float4*)&sT[chunk * 4];
        }
        #pragma unroll 1
        for (int pass = 0; pass < 8; pass++) {
            int m = pass * 16 + mloc;
            int node = nb + m;
            int deg = g_cur[node]; if (deg > BKT_CAP) deg = BKT_CAP;
            const int4* bq = &g_bkt4[(size_t)node * (BKT_CAP / 4)];
            int4 q0 = bq[0], q1 = bq[1], q2 = bq[2], q3 = bq[3];
            int idx[16] = {q0.x, q0.y, q0.z, q0.w, q1.x, q1.y, q1.z, q1.w,
                           q2.x, q2.y, q2.z, q2.w, q3.x, q3.y, q3.z, q3.w};
            float4 a = ((const float4*)(gsrc + (size_t)node * 64))[chunk];
            int jm = deg < 16 ? deg : 16;
            #pragma unroll
            for (int j = 0; j < 16; j++) {
                if (j < jm) {
                    float4 v = ((const float4*)(gsrc + (size_t)idx[j] * 64))[chunk];
                    a.x += v.x; a.y += v.y; a.z += v.z; a.w += v.w;
                }
            }
            for (int j = 16; j < deg; j++) {
                float4 v = ((const float4*)(gsrc + (size_t)((const int*)bq)[j] * 64))[chunk];
                a.x += v.x; a.y += v.y; a.z += v.z; a.w += v.w;
            }
            if (BNFOLD) {
                float fd = 1.f + (float)deg;
                a.x = sSv.x * a.x + fd * sTv.x;
                a.y = sSv.y * a.y + fd * sTv.y;
                a.z = sSv.z * a.z + fd * sTv.z;
                a.w = sSv.w * a.w + fd * sTv.w;
            }
            int mg = m >> 2, mr = m & 3;
            #pragma unroll
            for (int l = 0; l < 4; l++) {
                int k = chunk * 4 + l;
                int g = mg ^ ((k >> 3) & 7);
                sAT[k * 128 + (g << 2) + mr] = (&a.x)[l];
            }
        }
    }
    __syncthreads();

    const int mt = tid >> 4;   // 0..15, m_base = mt*8
    const int nt = tid & 15;   // 0..15, n_base = nt*4

    float2 acc[8][2];
    #pragma unroll
    for (int i = 0; i < 8; i++) { acc[i][0] = make_float2(0.f, 0.f); acc[i][1] = make_float2(0.f, 0.f); }

    // ---- GEMM1: [128 x KIN] @ [KIN x 64] ----
    #pragma unroll 4
    for (int k = 0; k < KIN; k++) {
        int swz = (k >> 3) & 7;
        float4 aA = *(const float4*)&sAT[k * 128 + (((2 * mt    ) ^ swz) << 2)];
        float4 aB = *(const float4*)&sAT[k * 128 + (((2 * mt + 1) ^ swz) << 2)];
        float4 b  = *(const float4*)&sW[k * 64 + nt * 4];
        float2 b0 = make_float2(b.x, b.y), b1 = make_float2(b.z, b.w);
        float am[8] = {aA.x, aA.y, aA.z, aA.w, aB.x, aB.y, aB.z, aB.w};
        #pragma unroll
        for (int i = 0; i < 8; i++) {
            float2 ai = make_float2(am[i], am[i]);
            ffma2(acc[i][0], ai, b0);
            ffma2(acc[i][1], ai, b1);
        }
    }

    float bj[4];
    #pragma unroll
    for (int j = 0; j < 4; j++) bj[j] = sBias[nt * 4 + j];
    __syncthreads();   // done reading sAT / sW / sBias

    // ---- mid: relu(acc + b1) -> sAT (k = mid channel); reload W2/b2 ----
    #pragma unroll
    for (int j = 0; j < 4; j++) {
        int k2 = nt * 4 + j;
        int jj = j >> 1;
        float v0, v1, v2, v3, v4, v5, v6, v7;
        if (j & 1) {
            v0 = acc[0][jj].y; v1 = acc[1][jj].y; v2 = acc[2][jj].y; v3 = acc[3][jj].y;
            v4 = acc[4][jj].y; v5 = acc[5][jj].y; v6 = acc[6][jj].y; v7 = acc[7][jj].y;
        } else {
            v0 = acc[0][jj].x; v1 = acc[1][jj].x; v2 = acc[2][jj].x; v3 = acc[3][jj].x;
            v4 = acc[4][jj].x; v5 = acc[5][jj].x; v6 = acc[6][jj].x; v7 = acc[7][jj].x;
        }
        float b = bj[j];
        float4 lo = make_float4(fmaxf(v0 + b, 0.f), fmaxf(v1 + b, 0.f),
                                fmaxf(v2 + b, 0.f), fmaxf(v3 + b, 0.f));
        float4 hi = make_float4(fmaxf(v4 + b, 0.f), fmaxf(v5 + b, 0.f),
                                fmaxf(v6 + b, 0.f), fmaxf(v7 + b, 0.f));
        int swz2 = (k2 >> 3) & 7;
        *(float4*)&sAT[k2 * 128 + (((2 * mt    ) ^ swz2) << 2)] = lo;
        *(float4*)&sAT[k2 * 128 + (((2 * mt + 1) ^ swz2) << 2)] = hi;
    }
    for (int i = tid; i < 64 * 64; i += 256) sW[i] = Wb[i];
    if (tid < 64) sBias[tid] = bb[tid];
    __syncthreads();

    #pragma unroll
    for (int i = 0; i < 8; i++) { acc[i][0] = make_float2(0.f, 0.f); acc[i][1] = make_float2(0.f, 0.f); }

    // ---- GEMM2: [128 x 64] @ [64 x 64] ----
    #pragma unroll 8
    for (int k = 0; k < 64; k++) {
        int swz = (k >> 3) & 7;
        float4 aA = *(const float4*)&sAT[k * 128 + (((2 * mt    ) ^ swz) << 2)];
        float4 aB = *(const float4*)&sAT[k * 128 + (((2 * mt + 1) ^ swz) << 2)];
        float4 b  = *(const float4*)&sW[k * 64 + nt * 4];
        float2 b0 = make_float2(b.x, b.y), b1 = make_float2(b.z, b.w);
        float am[8] = {aA.x, aA.y, aA.z, aA.w, aB.x, aB.y, aB.z, aB.w};
        #pragma unroll
        for (int i = 0; i < 8; i++) {
            float2 ai = make_float2(am[i], am[i]);
            ffma2(acc[i][0], ai, b0);
            ffma2(acc[i][1], ai, b1);
        }
    }

    float cj[4];
    #pragma unroll
    for (int j = 0; j < 4; j++) cj[j] = sBias[nt * 4 + j];

    // ---- epilogue: relu + store + BN stats ----
    float psum[4] = {0.f, 0.f, 0.f, 0.f};
    float psq[4]  = {0.f, 0.f, 0.f, 0.f};

    #pragma unroll
    for (int i = 0; i < 8; i++) {
        float4 v;
        v.x = fmaxf(acc[i][0].x + cj[0], 0.f);
        v.y = fmaxf(acc[i][0].y + cj[1], 0.f);
        v.z = fmaxf(acc[i][1].x + cj[2], 0.f);
        v.w = fmaxf(acc[i][1].y + cj[3], 0.f);
        size_t row = (size_t)(nb + mt * 8 + i) * 64 + (size_t)nt * 4;
        *(float4*)&gout[row] = v;
        psum[0] += v.x; psq[0] += v.x * v.x;
        psum[1] += v.y; psq[1] += v.y * v.y;
        psum[2] += v.z; psq[2] += v.z * v.z;
        psum[3] += v.w; psq[3] += v.w * v.w;
    }

    // reduce mt-pair within warp (tid bit4), then shared atomics
    #pragma unroll
    for (int j = 0; j < 4; j++) {
        psum[j] += __shfl_xor_sync(0xffffffffu, psum[j], 16);
        psq[j]  += __shfl_xor_sync(0xffffffffu, psq[j], 16);
    }
    if ((tid & 16) == 0) {
        #pragma unroll
        for (int j = 0; j < 4; j++) {
            atomicAdd(&sStat[nt * 4 + j], psum[j]);
            atomicAdd(&sStat[64 + nt * 4 + j], psq[j]);
        }
    }
    __syncthreads();
    if (tid < 128) atomicAdd(&g_stat[stat_out_off + tid], sStat[tid]);
}

// -------- final: BN3 + per-graph sum-pool + fc (reads g_hA) --------
__global__ __launch_bounds__(64) void k_final(
    const float* __restrict__ g3, const float* __restrict__ be3,
    const float* __restrict__ Wfc, const float* __restrict__ bfc,
    float* __restrict__ out)
{
    int g = blockIdx.x;
    int c = threadIdx.x;  // 0..63

    float sum = g_stat[4 * 64 + c];
    float sq  = g_stat[5 * 64 + c];
    float mean = sum / FN;
    float var  = sq / FN - mean * mean;
    float inv  = rsqrtf(var + BN_EPS);
    float s    = g3[c] * inv;
    float t    = be3[c] - mean * s;

    const float* base = g_hA + (size_t)g * NPG * 64;
    float acc = 0.f;
    #pragma unroll 2
    for (int i = 0; i < NPG; i++) acc += base[(size_t)i * 64 + c];
    float pool = s * acc + (float)NPG * t;

    __shared__ float red[3][64];
    red[0][c] = pool * Wfc[c * 3 + 0];
    red[1][c] = pool * Wfc[c * 3 + 1];
    red[2][c] = pool * Wfc[c * 3 + 2];
    __syncthreads();
    if (c < 3) {
        float a = 0.f;
        #pragma unroll
        for (int i = 0; i < 64; i++) a += red[c][i];
        out[(size_t)g * 3 + c] = a + bfc[c];
    }
}

// -------- launch --------
extern "C" void kernel_launch(void* const* d_in, const int* in_sizes, int n_in,
                              void* d_out, int out_size) {
    (void)in_sizes; (void)n_in; (void)out_size;
    const float* x   = (const float*)d_in[0];
    const int*   src = (const int*)d_in[1];
    const int*   dst = (const int*)d_in[2];
    const float* W1a = (const float*)d_in[4];
    const float* b1a = (const float*)d_in[5];
    const float* W1b = (const float*)d_in[6];
    const float* b1b = (const float*)d_in[7];
    const float* g1  = (const float*)d_in[8];
    const float* be1 = (const float*)d_in[9];
    const float* W2a = (const float*)d_in[10];
    const float* b2a = (const float*)d_in[11];
    const float* W2b = (const float*)d_in[12];
    const float* b2b = (const float*)d_in[13];
    const float* g2  = (const float*)d_in[14];
    const float* be2 = (const float*)d_in[15];
    const float* W3a = (const float*)d_in[16];
    const float* b3a = (const float*)d_in[17];
    const float* W3b = (const float*)d_in[18];
    const float* b3b = (const float*)d_in[19];
    const float* g3  = (const float*)d_in[20];
    const float* be3 = (const float*)d_in[21];
    const float* Wfc = (const float*)d_in[22];
    const float* bfc = (const float*)d_in[23];
    float* out = (float*)d_out;

    // opt-in >48KB dynamic smem (host attribute set — capture-safe, idempotent)
    cudaFuncSetAttribute(k_mlp<4, false>, cudaFuncAttributeMaxDynamicSharedMemorySize, SMEM_BYTES);
    cudaFuncSetAttribute(k_mlp<64, true>, cudaFuncAttributeMaxDynamicSharedMemorySize, SMEM_BYTES);

    const int TPB = 256;
    k_zero<<<(NNODES + TPB - 1) / TPB, TPB>>>();
    k_scatter<<<(NEDGES + TPB - 1) / TPB, TPB>>>(src, dst);

    // layer 1: input x (4ch) -> writes A
    k_mlp<4, false><<<NNODES / MTILE, 256, SMEM_BYTES>>>(x, 0, 0, W1a, b1a, W1b, b1b, nullptr, nullptr, 0, 0);
    // layer 2: gather from A + fold BN1 -> writes B
    k_mlp<64, true><<<NNODES / MTILE, 256, SMEM_BYTES>>>(nullptr, 0, 1, W2a, b2a, W2b, b2b, g1, be1, 0, 128);
    // layer 3: gather from B + fold BN2 -> writes A
    k_mlp<64, true><<<NNODES / MTILE, 256, SMEM_BYTES>>>(nullptr, 1, 0, W3a, b3a, W3b, b3b, g2, be2, 128, 256);

    // BN3 + pool + classifier (reads A)
    k_final<<<NGRAPHS, 64>>>(g3, be3, Wfc, bfc, out);
}

// round 12
// speedup vs baseline: 1.8484x; 1.0081x over previous
#include <cuda_runtime.h>

#define NNODES 507904
#define NEDGES 4063232
#define HID 64
#define NGRAPHS 8192
#define NPG 62
#define BN_EPS 1e-5f
#define FN ((float)NNODES)
#define BKT_CAP 64
#define MTILE 128

// dynamic smem (floats):
// sAT[8192] | sW[4096] | sBias[64] | sS[64] | sT[64] | sStat[128]  = 12608 floats
#define SMEM_FLOATS (8192 + 4096 + 64 + 64 + 64 + 128)
#define SMEM_BYTES  (SMEM_FLOATS * 4)

// -------- device scratch (no allocations allowed) --------
__device__ float g_hA[(size_t)NNODES * HID];        // activation buffer A
__device__ float g_hB[(size_t)NNODES * HID];        // activation buffer B
__device__ int4  g_bkt4[(size_t)NNODES * (BKT_CAP / 4)];  // bucket lists (16B aligned)
__device__ int   g_cur[NNODES];                     // bucket cursor == in-degree
__device__ float g_stat[6 * HID];                   // [sum0,sq0, sum1,sq1, sum2,sq2]

// packed fp32 FMA (Blackwell f32x2): d = a*b + d
__device__ __forceinline__ void ffma2(float2& d, float2 a, float2 b) {
    asm("{\n\t"
        ".reg .b64 ra, rb, rd;\n\t"
        "mov.b64 ra, {%2, %3};\n\t"
        "mov.b64 rb, {%4, %5};\n\t"
        "mov.b64 rd, {%0, %1};\n\t"
        "fma.rn.f32x2 rd, ra, rb, rd;\n\t"
        "mov.b64 {%0, %1}, rd;\n\t"
        "}"
        : "+f"(d.x), "+f"(d.y)
        : "f"(a.x), "f"(a.y), "f"(b.x), "f"(b.y));
}

// packed fp32 add (Blackwell f32x2): d = d + v
__device__ __forceinline__ void add2(float2& d, float2 v) {
    asm("{\n\t"
        ".reg .b64 rd, rv;\n\t"
        "mov.b64 rd, {%0, %1};\n\t"
        "mov.b64 rv, {%2, %3};\n\t"
        "add.rn.f32x2 rd, rd, rv;\n\t"
        "mov.b64 {%0, %1}, rd;\n\t"
        "}"
        : "+f"(d.x), "+f"(d.y)
        : "f"(v.x), "f"(v.y));
}

// -------- setup kernels --------
__global__ void k_zero() {
    int i = blockIdx.x * blockDim.x + threadIdx.x;
    if (i < NNODES) g_cur[i] = 0;
    if (i < 6 * HID) g_stat[i] = 0.f;
}

__global__ void k_scatter(const int2* __restrict__ src2, const int2* __restrict__ dst2) {
    int e = blockIdx.x * blockDim.x + threadIdx.x;
    if (e < NEDGES / 2) {
        int2 d = dst2[e];
        int2 s = src2[e];
        int p0 = atomicAdd(&g_cur[d.x], 1);
        if (p0 < BKT_CAP) ((int*)g_bkt4)[(size_t)d.x * BKT_CAP + p0] = s.x;
        int p1 = atomicAdd(&g_cur[d.y], 1);
        if (p1 < BKT_CAP) ((int*)g_bkt4)[(size_t)d.y * BKT_CAP + p1] = s.y;
    }
}

// -------- fused GIN layer --------
// 256 threads, 128 nodes/CTA. GEMM thread tile: 8 nodes x 4 channels.
// sAT: transposed A [k][m] fp32, XOR-swizzled:
//   float offset(k,m) = k*128 + ((((m>>2) ^ ((k>>3)&7)) << 2) | (m&3))
// sW: fp32 [k][n] straight layout (conflict-free broadcast B loads).
template<int KIN, bool BNFOLD>
__global__ __launch_bounds__(256, 4) void k_mlp(
    const float* __restrict__ xin, int srcsel, int dstsel,
    const float* __restrict__ Wa, const float* __restrict__ ba,
    const float* __restrict__ Wb, const float* __restrict__ bb,
    const float* __restrict__ gamma, const float* __restrict__ beta,
    int stat_in_off, int stat_out_off)
{
    extern __shared__ float smem[];
    float* sAT   = smem;                 // 8192 floats (32 KB)
    float* sW    = smem + 8192;          // 4096 floats (16 KB)
    float* sBias = smem + 8192 + 4096;   // 64
    float* sS    = sBias + 64;           // 64
    float* sT    = sS + 64;              // 64
    float* sStat = sT + 64;              // 128

    const int tid = threadIdx.x;
    const int nb = blockIdx.x * MTILE;
    const float* __restrict__ gsrc = srcsel ? g_hB : g_hA;
    float* __restrict__ gout = dstsel ? g_hB : g_hA;

    if (tid < 128) sStat[tid] = 0.f;
    if (BNFOLD && tid < 64) {
        float sum = g_stat[stat_in_off + tid];
        float sq  = g_stat[stat_in_off + 64 + tid];
        float mean = sum / FN;
        float var  = sq / FN - mean * mean;
        float inv  = rsqrtf(var + BN_EPS);
        float s    = gamma[tid] * inv;
        sS[tid] = s;
        sT[tid] = beta[tid] - mean * s;
    }
    if (tid < 64) sBias[tid] = ba[tid];
    for (int i = tid; i < KIN * 64; i += 256) sW[i] = Wa[i];
    __syncthreads();

    // ---- gather phase: neighbor sum (+BN fold) -> sAT (transposed, swizzled) ----
    if (KIN == 4) {
        if (tid < 128) {
            int m = tid;
            int node = nb + m;
            int deg = g_cur[node]; if (deg > BKT_CAP) deg = BKT_CAP;
            const int* bkt = (const int*)&g_bkt4[(size_t)node * (BKT_CAP / 4)];
            int4 q0 = ((const int4*)bkt)[0], q1 = ((const int4*)bkt)[1];
            int idx[8] = {q0.x, q0.y, q0.z, q0.w, q1.x, q1.y, q1.z, q1.w};
            float4 own = ((const float4*)xin)[node];
            float2 a01 = make_float2(own.x, own.y);
            float2 a23 = make_float2(own.z, own.w);
            #pragma unroll
            for (int j = 0; j < 8; j++) {
                if (j < deg) {
                    float4 v = ((const float4*)xin)[idx[j]];
                    add2(a01, make_float2(v.x, v.y));
                    add2(a23, make_float2(v.z, v.w));
                }
            }
            if (deg > 8) {
                int4 q2 = ((const int4*)bkt)[2], q3 = ((const int4*)bkt)[3];
                int idx2[8] = {q2.x, q2.y, q2.z, q2.w, q3.x, q3.y, q3.z, q3.w};
                #pragma unroll
                for (int j = 0; j < 8; j++) {
                    if (j + 8 < deg) {
                        float4 v = ((const float4*)xin)[idx2[j]];
                        add2(a01, make_float2(v.x, v.y));
                        add2(a23, make_float2(v.z, v.w));
                    }
                }
                for (int j = 16; j < deg; j++) {
                    float4 v = ((const float4*)xin)[bkt[j]];
                    add2(a01, make_float2(v.x, v.y));
                    add2(a23, make_float2(v.z, v.w));
                }
            }
            int base = ((m >> 2) << 2) | (m & 3);   // k<8 -> swz=0
            sAT[0 * 128 + base] = a01.x;
            sAT[1 * 128 + base] = a01.y;
            sAT[2 * 128 + base] = a23.x;
            sAT[3 * 128 + base] = a23.y;
        }
    } else {
        const int chunk = tid & 15;   // float4 chunk: channels chunk*4..+3
        const int mloc  = tid >> 4;   // 0..15
        float4 sSv, sTv;
        if (BNFOLD) {
            sSv = *(const float4*)&sS[chunk * 4];
            sTv = *(const float4*)&sT[chunk * 4];
        }
        #pragma unroll 1
        for (int pass = 0; pass < 8; pass++) {
            int m = pass * 16 + mloc;
            int node = nb + m;
            int deg = g_cur[node]; if (deg > BKT_CAP) deg = BKT_CAP;
            const int* bkt = (const int*)&g_bkt4[(size_t)node * (BKT_CAP / 4)];
            int4 q0 = ((const int4*)bkt)[0], q1 = ((const int4*)bkt)[1];
            int idx[8] = {q0.x, q0.y, q0.z, q0.w, q1.x, q1.y, q1.z, q1.w};
            float4 own = ((const float4*)(gsrc + (size_t)node * 64))[chunk];
            float2 a01 = make_float2(own.x, own.y);
            float2 a23 = make_float2(own.z, own.w);
            #pragma unroll
            for (int j = 0; j < 8; j++) {
                if (j < deg) {
                    float4 v = ((const float4*)(gsrc + (size_t)idx[j] * 64))[chunk];
                    add2(a01, make_float2(v.x, v.y));
                    add2(a23, make_float2(v.z, v.w));
                }
            }
            if (deg > 8) {
                int4 q2 = ((const int4*)bkt)[2], q3 = ((const int4*)bkt)[3];
                int idx2[8] = {q2.x, q2.y, q2.z, q2.w, q3.x, q3.y, q3.z, q3.w};
                #pragma unroll
                for (int j = 0; j < 8; j++) {
                    if (j + 8 < deg) {
                        float4 v = ((const float4*)(gsrc + (size_t)idx2[j] * 64))[chunk];
                        add2(a01, make_float2(v.x, v.y));
                        add2(a23, make_float2(v.z, v.w));
                    }
                }
                for (int j = 16; j < deg; j++) {
                    float4 v = ((const float4*)(gsrc + (size_t)bkt[j] * 64))[chunk];
                    add2(a01, make_float2(v.x, v.y));
                    add2(a23, make_float2(v.z, v.w));
                }
            }
            if (BNFOLD) {
                float fd = 1.f + (float)deg;
                float2 t01 = make_float2(fd * sTv.x, fd * sTv.y);
                float2 t23 = make_float2(fd * sTv.z, fd * sTv.w);
                ffma2(t01, a01, make_float2(sSv.x, sSv.y));
                ffma2(t23, a23, make_float2(sSv.z, sSv.w));
                a01 = t01; a23 = t23;
            }
            int mg = m >> 2, mr = m & 3;
            int k0 = chunk * 4;
            int g = mg ^ ((k0 >> 3) & 7);   // same swizzle group for all 4 k in chunk
            sAT[(k0 + 0) * 128 + (g << 2) + mr] = a01.x;
            sAT[(k0 + 1) * 128 + (g << 2) + mr] = a01.y;
            sAT[(k0 + 2) * 128 + (g << 2) + mr] = a23.x;
            sAT[(k0 + 3) * 128 + (g << 2) + mr] = a23.y;
        }
    }
    __syncthreads();

    const int mt = tid >> 4;   // 0..15, m_base = mt*8
    const int nt = tid & 15;   // 0..15, n_base = nt*4

    float2 acc[8][2];
    #pragma unroll
    for (int i = 0; i < 8; i++) { acc[i][0] = make_float2(0.f, 0.f); acc[i][1] = make_float2(0.f, 0.f); }

    // ---- GEMM1: [128 x KIN] @ [KIN x 64] ----
    #pragma unroll 4
    for (int k = 0; k < KIN; k++) {
        int swz = (k >> 3) & 7;
        float4 aA = *(const float4*)&sAT[k * 128 + (((2 * mt    ) ^ swz) << 2)];
        float4 aB = *(const float4*)&sAT[k * 128 + (((2 * mt + 1) ^ swz) << 2)];
        float4 b  = *(const float4*)&sW[k * 64 + nt * 4];
        float2 b0 = make_float2(b.x, b.y), b1 = make_float2(b.z, b.w);
        float am[8] = {aA.x, aA.y, aA.z, aA.w, aB.x, aB.y, aB.z, aB.w};
        #pragma unroll
        for (int i = 0; i < 8; i++) {
            float2 ai = make_float2(am[i], am[i]);
            ffma2(acc[i][0], ai, b0);
            ffma2(acc[i][1], ai, b1);
        }
    }

    float bj[4];
    #pragma unroll
    for (int j = 0; j < 4; j++) bj[j] = sBias[nt * 4 + j];
    __syncthreads();   // done reading sAT / sW / sBias

    // ---- mid: relu(acc + b1) -> sAT (k = mid channel); reload W2/b2 ----
    #pragma unroll
    for (int j = 0; j < 4; j++) {
        int k2 = nt * 4 + j;
        int jj = j >> 1;
        float v0, v1, v2, v3, v4, v5, v6, v7;
        if (j & 1) {
            v0 = acc[0][jj].y; v1 = acc[1][jj].y; v2 = acc[2][jj].y; v3 = acc[3][jj].y;
            v4 = acc[4][jj].y; v5 = acc[5][jj].y; v6 = acc[6][jj].y; v7 = acc[7][jj].y;
        } else {
            v0 = acc[0][jj].x; v1 = acc[1][jj].x; v2 = acc[2][jj].x; v3 = acc[3][jj].x;
            v4 = acc[4][jj].x; v5 = acc[5][jj].x; v6 = acc[6][jj].x; v7 = acc[7][jj].x;
        }
        float b = bj[j];
        float4 lo = make_float4(fmaxf(v0 + b, 0.f), fmaxf(v1 + b, 0.f),
                                fmaxf(v2 + b, 0.f), fmaxf(v3 + b, 0.f));
        float4 hi = make_float4(fmaxf(v4 + b, 0.f), fmaxf(v5 + b, 0.f),
                                fmaxf(v6 + b, 0.f), fmaxf(v7 + b, 0.f));
        int swz2 = (k2 >> 3) & 7;
        *(float4*)&sAT[k2 * 128 + (((2 * mt    ) ^ swz2) << 2)] = lo;
        *(float4*)&sAT[k2 * 128 + (((2 * mt + 1) ^ swz2) << 2)] = hi;
    }
    for (int i = tid; i < 64 * 64; i += 256) sW[i] = Wb[i];
    if (tid < 64) sBias[tid] = bb[tid];
    __syncthreads();

    #pragma unroll
    for (int i = 0; i < 8; i++) { acc[i][0] = make_float2(0.f, 0.f); acc[i][1] = make_float2(0.f, 0.f); }

    // ---- GEMM2: [128 x 64] @ [64 x 64] ----
    #pragma unroll 8
    for (int k = 0; k < 64; k++) {
        int swz = (k >> 3) & 7;
        float4 aA = *(const float4*)&sAT[k * 128 + (((2 * mt    ) ^ swz) << 2)];
        float4 aB = *(const float4*)&sAT[k * 128 + (((2 * mt + 1) ^ swz) << 2)];
        float4 b  = *(const float4*)&sW[k * 64 + nt * 4];
        float2 b0 = make_float2(b.x, b.y), b1 = make_float2(b.z, b.w);
        float am[8] = {aA.x, aA.y, aA.z, aA.w, aB.x, aB.y, aB.z, aB.w};
        #pragma unroll
        for (int i = 0; i < 8; i++) {
            float2 ai = make_float2(am[i], am[i]);
            ffma2(acc[i][0], ai, b0);
            ffma2(acc[i][1], ai, b1);
        }
    }

    float2 cj01 = make_float2(sBias[nt * 4 + 0], sBias[nt * 4 + 1]);
    float2 cj23 = make_float2(sBias[nt * 4 + 2], sBias[nt * 4 + 3]);

    // ---- epilogue: relu + store + BN stats (packed) ----
    float2 psum01 = make_float2(0.f, 0.f), psum23 = make_float2(0.f, 0.f);
    float2 psq01  = make_float2(0.f, 0.f), psq23  = make_float2(0.f, 0.f);

    #pragma unroll
    for (int i = 0; i < 8; i++) {
        add2(acc[i][0], cj01);
        add2(acc[i][1], cj23);
        float2 v01 = make_float2(fmaxf(acc[i][0].x, 0.f), fmaxf(acc[i][0].y, 0.f));
        float2 v23 = make_float2(fmaxf(acc[i][1].x, 0.f), fmaxf(acc[i][1].y, 0.f));
        size_t row = (size_t)(nb + mt * 8 + i) * 64 + (size_t)nt * 4;
        *(float4*)&gout[row] = make_float4(v01.x, v01.y, v23.x, v23.y);
        add2(psum01, v01); add2(psum23, v23);
        ffma2(psq01, v01, v01); ffma2(psq23, v23, v23);
    }

    float psum[4] = {psum01.x, psum01.y, psum23.x, psum23.y};
    float psq[4]  = {psq01.x, psq01.y, psq23.x, psq23.y};

    // reduce mt-pair within warp (tid bit4), then shared atomics
    #pragma unroll
    for (int j = 0; j < 4; j++) {
        psum[j] += __shfl_xor_sync(0xffffffffu, psum[j], 16);
        psq[j]  += __shfl_xor_sync(0xffffffffu, psq[j], 16);
    }
    if ((tid & 16) == 0) {
        #pragma unroll
        for (int j = 0; j < 4; j++) {
            atomicAdd(&sStat[nt * 4 + j], psum[j]);
            atomicAdd(&sStat[64 + nt * 4 + j], psq[j]);
        }
    }
    __syncthreads();
    if (tid < 128) atomicAdd(&g_stat[stat_out_off + tid], sStat[tid]);
}

// -------- final: BN3 + per-graph sum-pool + fc (reads g_hA) --------
__global__ __launch_bounds__(64) void k_final(
    const float* __restrict__ g3, const float* __restrict__ be3,
    const float* __restrict__ Wfc, const float* __restrict__ bfc,
    float* __restrict__ out)
{
    int g = blockIdx.x;
    int c = threadIdx.x;  // 0..63

    float sum = g_stat[4 * 64 + c];
    float sq  = g_stat[5 * 64 + c];
    float mean = sum / FN;
    float var  = sq / FN - mean * mean;
    float inv  = rsqrtf(var + BN_EPS);
    float s    = g3[c] * inv;
    float t    = be3[c] - mean * s;

    const float* base = g_hA + (size_t)g * NPG * 64;
    float acc = 0.f;
    #pragma unroll 2
    for (int i = 0; i < NPG; i++) acc += base[(size_t)i * 64 + c];
    float pool = s * acc + (float)NPG * t;

    __shared__ float red[3][64];
    red[0][c] = pool * Wfc[c * 3 + 0];
    red[1][c] = pool * Wfc[c * 3 + 1];
    red[2][c] = pool * Wfc[c * 3 + 2];
    __syncthreads();
    if (c < 3) {
        float a = 0.f;
        #pragma unroll
        for (int i = 0; i < 64; i++) a += red[c][i];
        out[(size_t)g * 3 + c] = a + bfc[c];
    }
}

// -------- launch --------
extern "C" void kernel_launch(void* const* d_in, const int* in_sizes, int n_in,
                              void* d_out, int out_size) {
    (void)in_sizes; (void)n_in; (void)out_size;
    const float* x   = (const float*)d_in[0];
    const int*   src = (const int*)d_in[1];
    const int*   dst = (const int*)d_in[2];
    const float* W1a = (const float*)d_in[4];
    const float* b1a = (const float*)d_in[5];
    const float* W1b = (const float*)d_in[6];
    const float* b1b = (const float*)d_in[7];
    const float* g1  = (const float*)d_in[8];
    const float* be1 = (const float*)d_in[9];
    const float* W2a = (const float*)d_in[10];
    const float* b2a = (const float*)d_in[11];
    const float* W2b = (const float*)d_in[12];
    const float* b2b = (const float*)d_in[13];
    const float* g2  = (const float*)d_in[14];
    const float* be2 = (const float*)d_in[15];
    const float* W3a = (const float*)d_in[16];
    const float* b3a = (const float*)d_in[17];
    const float* W3b = (const float*)d_in[18];
    const float* b3b = (const float*)d_in[19];
    const float* g3  = (const float*)d_in[20];
    const float* be3 = (const float*)d_in[21];
    const float* Wfc = (const float*)d_in[22];
    const float* bfc = (const float*)d_in[23];
    float* out = (float*)d_out;

    // opt-in >48KB dynamic smem (host attribute set — capture-safe, idempotent)
    cudaFuncSetAttribute(k_mlp<4, false>, cudaFuncAttributeMaxDynamicSharedMemorySize, SMEM_BYTES);
    cudaFuncSetAttribute(k_mlp<64, true>, cudaFuncAttributeMaxDynamicSharedMemorySize, SMEM_BYTES);

    const int TPB = 256;
    k_zero<<<(NNODES + TPB - 1) / TPB, TPB>>>();
    k_scatter<<<(NEDGES / 2 + TPB - 1) / TPB, TPB>>>((const int2*)src, (const int2*)dst);

    // layer 1: input x (4ch) -> writes A
    k_mlp<4, false><<<NNODES / MTILE, 256, SMEM_BYTES>>>(x, 0, 0, W1a, b1a, W1b, b1b, nullptr, nullptr, 0, 0);
    // layer 2: gather from A + fold BN1 -> writes B
    k_mlp<64, true><<<NNODES / MTILE, 256, SMEM_BYTES>>>(nullptr, 0, 1, W2a, b2a, W2b, b2b, g1, be1, 0, 128);
    // layer 3: gather from B + fold BN2 -> writes A
    k_mlp<64, true><<<NNODES / MTILE, 256, SMEM_BYTES>>>(nullptr, 1, 0, W3a, b3a, W3b, b3b, g2, be2, 128, 256);

    // BN3 + pool + classifier (reads A)
    k_final<<<NGRAPHS, 64>>>(g3, be3, Wfc, bfc, out);
}